// round 15
// baseline (speedup 1.0000x reference)
#include <cuda_runtime.h>
#include <cstdint>

// ---------------------------------------------------------------------------
// Problem: x[B,2] f32, ws[10] f32, B = 16777216.
//   step: nx0 = x0 - 0.1*x1
//         nx1 = (1 + 0.1*w)*x1 + 0.1*x0 - 0.1*x0^3
//   out  = (tanh(100(x1-0.1)) - tanh(100(x1+0.1)) + 2)/2
//
// Rescaled state: x0 = 10*p,  x1 = -100*nq  (track negated q)
//   p'  = p + nq
//   nq' = A*nq + nw,  nw = p*(p^2 - 0.01),  A = 1 + 0.1*w
// 4-op packed-f32x2 step, rt-weighted cost 9/step/chain on the banked pipe.
// Epilogue: 100*x1 -+ 10 = -10000*nq -+ 10 -> FFMA-imm (rt1) + MUFU.TANH.
//
// R14: 16 points/thread = 8 independent packed chains, MLP_p1 = 8
// (8 front-batched LDG.128). Kernel was latency-bound (no pipe >70%):
// deeper per-warp load queues + halved warp count attack exposed latency
// and per-point overhead. Streaming .cs hints retained; coefficients
// A[k] built per block in smem (single-kernel graph).
// ---------------------------------------------------------------------------

#define FMA2(d, a, b, c) \
    asm("fma.rn.f32x2 %0, %1, %2, %3;" : "=l"(d) : "l"(a), "l"(b), "l"(c))
#define MUL2(d, a, b) \
    asm("mul.rn.f32x2 %0, %1, %2;" : "=l"(d) : "l"(a), "l"(b))
#define ADD2(d, a, b) \
    asm("add.rn.f32x2 %0, %1, %2;" : "=l"(d) : "l"(a), "l"(b))

// Streaming (evict-first) 128-bit load/store.
__device__ __forceinline__ float4 ldcs4(const float4* p) {
    float4 v;
    asm("ld.global.cs.v4.f32 {%0, %1, %2, %3}, [%4];"
        : "=f"(v.x), "=f"(v.y), "=f"(v.z), "=f"(v.w) : "l"(p));
    return v;
}
__device__ __forceinline__ void stcs4(float4* p, float4 v) {
    asm("st.global.cs.v4.f32 [%0], {%1, %2, %3, %4};"
        :: "l"(p), "f"(v.x), "f"(v.y), "f"(v.z), "f"(v.w) : "memory");
}

__device__ __forceinline__ float tanh_approx(float x) {
    float r; asm("tanh.approx.f32 %0, %1;" : "=f"(r) : "f"(x)); return r;
}

// out = 0.5*(tanh(-10000*nq - 10) - tanh(-10000*nq + 10)) + 1
__device__ __forceinline__ float notch_nq(float nq) {
    float t1 = tanh_approx(fmaf(-10000.0f, nq, -10.0f));
    float t2 = tanh_approx(fmaf(-10000.0f, nq,  10.0f));
    return fmaf(0.5f, t1 - t2, 1.0f);
}

// Pack two floats' low words into one 64-bit pair register.
#define PACK2(d, lo, hi) \
    asm("mov.b64 %0, {%1, %2};" : "=l"(d) : "f"(lo), "f"(hi))
#define UNPACK2(lo, hi, s) \
    asm("mov.b64 {%0, %1}, %2;" : "=f"(lo), "=f"(hi) : "l"(s))

__global__ __launch_bounds__(256) void nn_kernel(
    const float4* __restrict__ x, const float* __restrict__ ws,
    float4* __restrict__ out, int n16)
{
    __shared__ unsigned long long sA[10];

    // Per-block coefficient prep: A[k] = splat(1 + 0.1*ws[k]).
    if (threadIdx.x < 10) {
        float a = fmaf(0.1f, __ldg(ws + threadIdx.x), 1.0f);
        unsigned int u = __float_as_uint(a);
        sA[threadIdx.x] = ((unsigned long long)u << 32) | (unsigned long long)u;
    }

    int i = blockIdx.x * blockDim.x + threadIdx.x;

    // Front-batched streaming loads (MLP_p1 = 8): 128B contiguous per
    // thread, 4KB contiguous per warp. Latency overlaps the barrier below.
    float4 v0, v1, v2, v3, v4, v5, v6, v7;
    if (i < n16) {
        const float4* xp = x + 8 * (long)i;
        v0 = ldcs4(xp + 0);  v1 = ldcs4(xp + 1);
        v2 = ldcs4(xp + 2);  v3 = ldcs4(xp + 3);
        v4 = ldcs4(xp + 4);  v5 = ldcs4(xp + 5);
        v6 = ldcs4(xp + 6);  v7 = ldcs4(xp + 7);
    }

    __syncthreads();

    if (i >= n16) return;

    const unsigned long long C01   = 0x3DCCCCCD3DCCCCCDULL;  // splat(+0.1f)
    const unsigned long long NC001 = 0xBC23D70ABC23D70AULL;  // splat(-0.01f)

    // Pack & scale into (p, nq): p = 0.1*x0, nq = -0.01*x1.
    unsigned long long P[8], NQ[8];
    {
        unsigned long long t0, t1;
        PACK2(t0, v0.x, v0.z); PACK2(t1, v0.y, v0.w);
        MUL2(P[0], t0, C01);   MUL2(NQ[0], t1, NC001);
        PACK2(t0, v1.x, v1.z); PACK2(t1, v1.y, v1.w);
        MUL2(P[1], t0, C01);   MUL2(NQ[1], t1, NC001);
        PACK2(t0, v2.x, v2.z); PACK2(t1, v2.y, v2.w);
        MUL2(P[2], t0, C01);   MUL2(NQ[2], t1, NC001);
        PACK2(t0, v3.x, v3.z); PACK2(t1, v3.y, v3.w);
        MUL2(P[3], t0, C01);   MUL2(NQ[3], t1, NC001);
        PACK2(t0, v4.x, v4.z); PACK2(t1, v4.y, v4.w);
        MUL2(P[4], t0, C01);   MUL2(NQ[4], t1, NC001);
        PACK2(t0, v5.x, v5.z); PACK2(t1, v5.y, v5.w);
        MUL2(P[5], t0, C01);   MUL2(NQ[5], t1, NC001);
        PACK2(t0, v6.x, v6.z); PACK2(t1, v6.y, v6.w);
        MUL2(P[6], t0, C01);   MUL2(NQ[6], t1, NC001);
        PACK2(t0, v7.x, v7.z); PACK2(t1, v7.y, v7.w);
        MUL2(P[7], t0, C01);   MUL2(NQ[7], t1, NC001);
    }

    #pragma unroll
    for (int k = 0; k < 10; k++) {
        unsigned long long A = sA[k];  // immediate-offset LDS, broadcast

        unsigned long long in[8], nw[8], p2[8];
        // Eight independent chains, phase-interleaved for ILP.
        #pragma unroll
        for (int c = 0; c < 8; c++) FMA2(in[c], P[c], P[c], NC001);  // p^2-0.01
        #pragma unroll
        for (int c = 0; c < 8; c++) MUL2(nw[c], in[c], P[c]);        // -w
        #pragma unroll
        for (int c = 0; c < 8; c++) ADD2(p2[c], P[c], NQ[c]);        // p' = p-q
        #pragma unroll
        for (int c = 0; c < 8; c++) {
            unsigned long long nq2;
            FMA2(nq2, A, NQ[c], nw[c]);                              // nq'
            P[c] = p2[c];  NQ[c] = nq2;
        }
    }

    // Epilogue: 16 notch evaluations, 4 streaming float4 stores.
    float4* op = out + 4 * (long)i;
    #pragma unroll
    for (int c = 0; c < 8; c += 2) {
        float a0, a1, b0, b1;
        UNPACK2(a0, a1, NQ[c]);
        UNPACK2(b0, b1, NQ[c + 1]);
        float4 o;
        o.x = notch_nq(a0);  o.y = notch_nq(a1);
        o.z = notch_nq(b0);  o.w = notch_nq(b1);
        stcs4(op + (c >> 1), o);
    }
}

extern "C" void kernel_launch(void* const* d_in, const int* in_sizes, int n_in,
                              void* d_out, int out_size) {
    // Robust input identification: ws is the 10-element tensor.
    const float* x;
    const float* ws;
    if (n_in >= 2 && in_sizes[0] == 10) {
        ws = (const float*)d_in[0];
        x  = (const float*)d_in[1];
    } else {
        x  = (const float*)d_in[0];
        ws = (const float*)d_in[1];
    }

    int n16 = out_size / 16;  // 16 points per thread (B = 2^24, divisible)
    int blocks = (n16 + 255) / 256;
    nn_kernel<<<blocks, 256>>>((const float4*)x, ws, (float4*)d_out, n16);
}

// round 16
// speedup vs baseline: 1.5333x; 1.5333x over previous
#include <cuda_runtime.h>
#include <cstdint>

// ---------------------------------------------------------------------------
// Problem: x[B,2] f32, ws[10] f32, B = 16777216.
//   step: nx0 = x0 - 0.1*x1
//         nx1 = (1 + 0.1*w)*x1 + 0.1*x0 - 0.1*x0^3
//   out  = (tanh(100(x1-0.1)) - tanh(100(x1+0.1)) + 2)/2
//
// Rescaled state: x0 = 10*p,  x1 = -100*nq  (track negated q)
//   p'  = p + nq
//   nq' = A*nq + nw,  nw = p*(p^2 - 0.01),  A = 1 + 0.1*w
// 4-op packed-f32x2 step, rt-weighted cost 9/step/chain on the banked pipe.
// Epilogue: 100*x1 -+ 10 = -10000*nq -+ 10 -> FFMA-imm (rt1) + MUFU.TANH.
//
// FINAL configuration (R13 winner, reverted after R15's regression):
//   8 points/thread = 4 independent packed chains, MLP_p1 = 4.
//   Sweep evidence: 4 pts -> 31.7us, 8 pts -> 29.1us, 16 pts -> 45.5us
//   (16-pt blowup = L1tex wavefront-queue contention: 8 LDG.128/warp x
//   64 wavefronts >> queue threshold; latency exposed, not hidden).
//   Streaming .cs on the one-touch 201MB stream; coefficients A[k] built
//   per block in smem (single kernel node in the graph).
// ---------------------------------------------------------------------------

#define FMA2(d, a, b, c) \
    asm("fma.rn.f32x2 %0, %1, %2, %3;" : "=l"(d) : "l"(a), "l"(b), "l"(c))
#define MUL2(d, a, b) \
    asm("mul.rn.f32x2 %0, %1, %2;" : "=l"(d) : "l"(a), "l"(b))
#define ADD2(d, a, b) \
    asm("add.rn.f32x2 %0, %1, %2;" : "=l"(d) : "l"(a), "l"(b))

// Streaming (evict-first) 128-bit load/store.
__device__ __forceinline__ float4 ldcs4(const float4* p) {
    float4 v;
    asm("ld.global.cs.v4.f32 {%0, %1, %2, %3}, [%4];"
        : "=f"(v.x), "=f"(v.y), "=f"(v.z), "=f"(v.w) : "l"(p));
    return v;
}
__device__ __forceinline__ void stcs4(float4* p, float4 v) {
    asm("st.global.cs.v4.f32 [%0], {%1, %2, %3, %4};"
        :: "l"(p), "f"(v.x), "f"(v.y), "f"(v.z), "f"(v.w) : "memory");
}

__device__ __forceinline__ float tanh_approx(float x) {
    float r; asm("tanh.approx.f32 %0, %1;" : "=f"(r) : "f"(x)); return r;
}

// out = 0.5*(tanh(-10000*nq - 10) - tanh(-10000*nq + 10)) + 1
__device__ __forceinline__ float notch_nq(float nq) {
    float t1 = tanh_approx(fmaf(-10000.0f, nq, -10.0f));
    float t2 = tanh_approx(fmaf(-10000.0f, nq,  10.0f));
    return fmaf(0.5f, t1 - t2, 1.0f);
}

__global__ __launch_bounds__(256) void nn_kernel(
    const float4* __restrict__ x, const float* __restrict__ ws,
    float4* __restrict__ out, int n8)
{
    __shared__ unsigned long long sA[10];

    // Per-block coefficient prep: A[k] = splat(1 + 0.1*ws[k]).
    if (threadIdx.x < 10) {
        float a = fmaf(0.1f, __ldg(ws + threadIdx.x), 1.0f);
        unsigned int u = __float_as_uint(a);
        sA[threadIdx.x] = ((unsigned long long)u << 32) | (unsigned long long)u;
    }

    int i = blockIdx.x * blockDim.x + threadIdx.x;

    // Front-batched streaming loads (MLP_p1 = 4): 64B contiguous per thread,
    // 2KB contiguous per warp. Latency overlaps the barrier below.
    float4 va, vb, vc, vd;
    if (i < n8) {
        const float4* xp = x + 4 * (long)i;
        va = ldcs4(xp + 0);  // points 0,1
        vb = ldcs4(xp + 1);  // points 2,3
        vc = ldcs4(xp + 2);  // points 4,5
        vd = ldcs4(xp + 3);  // points 6,7
    }

    __syncthreads();

    if (i >= n8) return;

    unsigned long long X0a, X1a, X0b, X1b, X0c, X1c, X0d, X1d;
    asm("mov.b64 %0, {%1, %2};" : "=l"(X0a) : "f"(va.x), "f"(va.z));
    asm("mov.b64 %0, {%1, %2};" : "=l"(X1a) : "f"(va.y), "f"(va.w));
    asm("mov.b64 %0, {%1, %2};" : "=l"(X0b) : "f"(vb.x), "f"(vb.z));
    asm("mov.b64 %0, {%1, %2};" : "=l"(X1b) : "f"(vb.y), "f"(vb.w));
    asm("mov.b64 %0, {%1, %2};" : "=l"(X0c) : "f"(vc.x), "f"(vc.z));
    asm("mov.b64 %0, {%1, %2};" : "=l"(X1c) : "f"(vc.y), "f"(vc.w));
    asm("mov.b64 %0, {%1, %2};" : "=l"(X0d) : "f"(vd.x), "f"(vd.z));
    asm("mov.b64 %0, {%1, %2};" : "=l"(X1d) : "f"(vd.y), "f"(vd.w));

    const unsigned long long C01   = 0x3DCCCCCD3DCCCCCDULL;  // splat(+0.1f)
    const unsigned long long NC001 = 0xBC23D70ABC23D70AULL;  // splat(-0.01f)

    // Scale into (p, nq): p = 0.1*x0, nq = -0.01*x1
    unsigned long long Pa, NQa, Pb, NQb, Pc, NQc, Pd, NQd;
    MUL2(Pa,  X0a, C01);   MUL2(NQa, X1a, NC001);
    MUL2(Pb,  X0b, C01);   MUL2(NQb, X1b, NC001);
    MUL2(Pc,  X0c, C01);   MUL2(NQc, X1c, NC001);
    MUL2(Pd,  X0d, C01);   MUL2(NQd, X1d, NC001);

    #pragma unroll
    for (int k = 0; k < 10; k++) {
        unsigned long long A = sA[k];  // immediate-offset LDS, broadcast

        unsigned long long ina, nwa, pa2, nqa2;
        unsigned long long inb, nwb, pb2, nqb2;
        unsigned long long inc, nwc, pc2, nqc2;
        unsigned long long ind, nwd, pd2, nqd2;
        // Four independent chains interleaved for ILP.
        FMA2(ina,  Pa, Pa, NC001);    // p^2 - 0.01
        FMA2(inb,  Pb, Pb, NC001);
        FMA2(inc,  Pc, Pc, NC001);
        FMA2(ind,  Pd, Pd, NC001);
        MUL2(nwa,  ina, Pa);          // p^3 - 0.01p = -w
        MUL2(nwb,  inb, Pb);
        MUL2(nwc,  inc, Pc);
        MUL2(nwd,  ind, Pd);
        ADD2(pa2,  Pa, NQa);          // p' = p - q
        ADD2(pb2,  Pb, NQb);
        ADD2(pc2,  Pc, NQc);
        ADD2(pd2,  Pd, NQd);
        FMA2(nqa2, A, NQa, nwa);      // nq' = A*nq - w
        FMA2(nqb2, A, NQb, nwb);
        FMA2(nqc2, A, NQc, nwc);
        FMA2(nqd2, A, NQd, nwd);
        Pa = pa2;  NQa = nqa2;
        Pb = pb2;  NQb = nqb2;
        Pc = pc2;  NQc = nqc2;
        Pd = pd2;  NQd = nqd2;
    }

    float q0, q1, q2, q3, q4, q5, q6, q7;
    asm("mov.b64 {%0, %1}, %2;" : "=f"(q0), "=f"(q1) : "l"(NQa));
    asm("mov.b64 {%0, %1}, %2;" : "=f"(q2), "=f"(q3) : "l"(NQb));
    asm("mov.b64 {%0, %1}, %2;" : "=f"(q4), "=f"(q5) : "l"(NQc));
    asm("mov.b64 {%0, %1}, %2;" : "=f"(q6), "=f"(q7) : "l"(NQd));

    float4 o0, o1;
    o0.x = notch_nq(q0);  o0.y = notch_nq(q1);
    o0.z = notch_nq(q2);  o0.w = notch_nq(q3);
    o1.x = notch_nq(q4);  o1.y = notch_nq(q5);
    o1.z = notch_nq(q6);  o1.w = notch_nq(q7);

    float4* op = out + 2 * (long)i;
    stcs4(op + 0, o0);   // 2x 16B streaming stores of 8 outputs
    stcs4(op + 1, o1);
}

extern "C" void kernel_launch(void* const* d_in, const int* in_sizes, int n_in,
                              void* d_out, int out_size) {
    // Robust input identification: ws is the 10-element tensor.
    const float* x;
    const float* ws;
    if (n_in >= 2 && in_sizes[0] == 10) {
        ws = (const float*)d_in[0];
        x  = (const float*)d_in[1];
    } else {
        x  = (const float*)d_in[0];
        ws = (const float*)d_in[1];
    }

    int n8 = out_size / 8;  // 8 points per thread (B = 2^24, divisible)
    int blocks = (n8 + 255) / 256;
    nn_kernel<<<blocks, 256>>>((const float4*)x, ws, (float4*)d_out, n8);
}